// round 3
// baseline (speedup 1.0000x reference)
#include <cuda_runtime.h>
#include <math.h>

#define S4 4
#define CD 512
#define KD 128
#define HW 1024
#define NM 16384
#define CE 16
#define TAU_INV 30.0f
#define KSPLIT 8

typedef unsigned long long ull;

__device__ __forceinline__ void fma2(ull& d, ull a, ull b) {
  asm("fma.rn.f32x2 %0, %1, %2, %0;" : "+l"(d) : "l"(a), "l"(b));
}
__device__ __forceinline__ float red2(ull v) {
  float lo, hi;
  asm("mov.b64 {%0,%1}, %2;" : "=f"(lo), "=f"(hi) : "l"(v));
  return lo + hi;
}
__device__ __forceinline__ ull dup2(float x) {
  ull r; asm("mov.b64 %0, {%1,%1};" : "=l"(r) : "f"(x)); return r;
}

// ---------------- scratch (device globals; no allocation allowed) ----------------
__device__ float g_wq_self[S4 * HW * KD];
__device__ float g_sc[S4 * HW * HW];
__device__ float g_t[S4 * CD * HW];
__device__ float g_wq_cross[S4 * HW * KD];
__device__ float g_wk_cross[S4 * NM * KD];
__device__ float g_part[KSPLIT * S4 * HW * 18];

// ================= projection + L2 normalize =================
// in layout: [(f*S + s)*CD + c]*HW + n ; out [s][token][d]
__global__ __launch_bounds__(256) void proj_kernel(
    const float* __restrict__ in, const float* __restrict__ W,
    const float* __restrict__ bias, float* __restrict__ out, int NT) {
  __shared__ float As[32 * 36];    // [tok][cc]
  __shared__ float Ws[128 * 36];   // [d][cc]
  __shared__ float Ys[32][129];    // [tok][d]
  int s = blockIdx.y;
  int tg0 = blockIdx.x * 32;
  int f = tg0 >> 10;
  int n0 = tg0 & 1023;
  const float* inb = in + ((size_t)(f * S4 + s)) * CD * HW + n0;
  int t = threadIdx.x;
  int tgq = t & 7;     // token group (4 tokens each)
  int dg  = t >> 3;    // d group (4 d each)
  ull acc[4][4] = {};
  for (int c0 = 0; c0 < CD; c0 += 32) {
    int idx = t;
    #pragma unroll
    for (int r = 0; r < 4; r++, idx += 256) {
      int cc = idx >> 5, tok = idx & 31;
      As[tok * 36 + cc] = inb[(size_t)(c0 + cc) * HW + tok];
    }
    idx = t;
    #pragma unroll
    for (int r = 0; r < 16; r++, idx += 256) {
      int d = idx >> 5, cc = idx & 31;
      Ws[d * 36 + cc] = W[d * CD + c0 + cc];
    }
    __syncthreads();
    #pragma unroll
    for (int k4 = 0; k4 < 8; k4++) {
      ulonglong2 a[4], b[4];
      #pragma unroll
      for (int i = 0; i < 4; i++)
        a[i] = *(const ulonglong2*)(As + (tgq * 4 + i) * 36 + k4 * 4);
      #pragma unroll
      for (int j = 0; j < 4; j++)
        b[j] = *(const ulonglong2*)(Ws + (dg * 4 + j) * 36 + k4 * 4);
      #pragma unroll
      for (int i = 0; i < 4; i++)
        #pragma unroll
        for (int j = 0; j < 4; j++) {
          fma2(acc[i][j], a[i].x, b[j].x);
          fma2(acc[i][j], a[i].y, b[j].y);
        }
    }
    __syncthreads();
  }
  #pragma unroll
  for (int j = 0; j < 4; j++) {
    float bb = bias[dg * 4 + j];
    #pragma unroll
    for (int i = 0; i < 4; i++)
      Ys[tgq * 4 + i][dg * 4 + j] = red2(acc[i][j]) + bb;
  }
  __syncthreads();
  int warp = t >> 5, lane = t & 31;
  #pragma unroll
  for (int r = 0; r < 4; r++) {
    int tt = warp * 4 + r;
    float v0 = Ys[tt][lane], v1 = Ys[tt][lane + 32];
    float v2 = Ys[tt][lane + 64], v3 = Ys[tt][lane + 96];
    float ss = v0 * v0 + v1 * v1 + v2 * v2 + v3 * v3;
    #pragma unroll
    for (int o = 16; o; o >>= 1) ss += __shfl_xor_sync(0xffffffffu, ss, o);
    float scl = 1.0f / fmaxf(sqrtf(ss), 1e-12f);
    float* ob = out + ((size_t)s * NT + tg0 + tt) * KD;
    ob[lane] = v0 * scl; ob[lane + 32] = v1 * scl;
    ob[lane + 64] = v2 * scl; ob[lane + 96] = v3 * scl;
  }
}

// ================= self-attention raw scores (x30) =================
__global__ __launch_bounds__(256) void self_scores_kernel(
    const float* __restrict__ wq, float* __restrict__ sc) {
  __shared__ float QK[2][64 * 68];
  int s = blockIdx.z;
  int q0 = blockIdx.x * 64, k0 = blockIdx.y * 64;
  const float* base = wq + (size_t)s * HW * KD;
  int t = threadIdx.x;
  int qg = t & 15, kg = t >> 4;
  ull acc[4][4] = {};
  for (int d0 = 0; d0 < KD; d0 += 64) {
    int idx = t;
    #pragma unroll
    for (int r = 0; r < 16; r++, idx += 256) {
      int row = idx >> 6, dd = idx & 63;
      QK[0][row * 68 + dd] = base[(size_t)(q0 + row) * KD + d0 + dd];
      QK[1][row * 68 + dd] = base[(size_t)(k0 + row) * KD + d0 + dd];
    }
    __syncthreads();
    #pragma unroll
    for (int d4 = 0; d4 < 16; d4++) {
      ulonglong2 a[4], b[4];
      #pragma unroll
      for (int i = 0; i < 4; i++)
        a[i] = *(const ulonglong2*)(&QK[0][(qg * 4 + i) * 68 + d4 * 4]);
      #pragma unroll
      for (int j = 0; j < 4; j++)
        b[j] = *(const ulonglong2*)(&QK[1][(kg * 4 + j) * 68 + d4 * 4]);
      #pragma unroll
      for (int i = 0; i < 4; i++)
        #pragma unroll
        for (int j = 0; j < 4; j++) {
          fma2(acc[i][j], a[i].x, b[j].x);
          fma2(acc[i][j], a[i].y, b[j].y);
        }
    }
    __syncthreads();
  }
  float* Cs = &QK[0][0];   // reuse as [64][65]
  #pragma unroll
  for (int i = 0; i < 4; i++)
    #pragma unroll
    for (int j = 0; j < 4; j++)
      Cs[(qg * 4 + i) * 65 + kg * 4 + j] = red2(acc[i][j]) * TAU_INV;
  __syncthreads();
  int idx = t;
  #pragma unroll
  for (int r = 0; r < 16; r++, idx += 256) {
    int row = idx >> 6, col = idx & 63;
    sc[((size_t)s * HW + q0 + row) * HW + k0 + col] = Cs[row * 65 + col];
  }
}

// ================= row softmax over 1024 =================
__global__ __launch_bounds__(256) void softmax_kernel(float* __restrict__ sc) {
  __shared__ float redm[8];
  __shared__ float reds[8];
  float* p = sc + (size_t)blockIdx.x * HW;
  int t = threadIdx.x, lane = t & 31, warp = t >> 5;
  float v0 = p[t], v1 = p[t + 256], v2 = p[t + 512], v3 = p[t + 768];
  float mx = fmaxf(fmaxf(v0, v1), fmaxf(v2, v3));
  #pragma unroll
  for (int o = 16; o; o >>= 1) mx = fmaxf(mx, __shfl_xor_sync(0xffffffffu, mx, o));
  if (lane == 0) redm[warp] = mx;
  __syncthreads();
  mx = redm[0];
  #pragma unroll
  for (int i = 1; i < 8; i++) mx = fmaxf(mx, redm[i]);
  v0 = __expf(v0 - mx); v1 = __expf(v1 - mx);
  v2 = __expf(v2 - mx); v3 = __expf(v3 - mx);
  float sum = v0 + v1 + v2 + v3;
  #pragma unroll
  for (int o = 16; o; o >>= 1) sum += __shfl_xor_sync(0xffffffffu, sum, o);
  if (lane == 0) reds[warp] = sum;
  __syncthreads();
  float tot = reds[0];
  #pragma unroll
  for (int i = 1; i < 8; i++) tot += reds[i];
  float inv = 1.0f / tot;
  p[t] = v0 * inv; p[t + 256] = v1 * inv;
  p[t + 512] = v2 * inv; p[t + 768] = v3 * inv;
}

// ================= self P.V + residual =================
__global__ __launch_bounds__(256) void pv_self_kernel(
    const float* __restrict__ sc, const float* __restrict__ tgt,
    float* __restrict__ tout) {
  __shared__ float As[64 * 36];   // [n][m]
  __shared__ float Bs[64 * 36];   // [c][m]
  __shared__ float Cs[64 * 65];   // [n][c] flat
  int s = blockIdx.z;
  int n0 = blockIdx.x * 64, c0 = blockIdx.y * 64;
  const float* P = sc + (size_t)s * HW * HW;
  const float* V = tgt + (size_t)s * CD * HW;
  int t = threadIdx.x;
  int ng = t & 15, cg = t >> 4;
  ull acc[4][4] = {};
  for (int m0 = 0; m0 < HW; m0 += 32) {
    int idx = t;
    #pragma unroll
    for (int r = 0; r < 8; r++, idx += 256) {
      int n = idx >> 5, m = idx & 31;
      As[n * 36 + m] = P[(size_t)(n0 + n) * HW + m0 + m];
    }
    idx = t;
    #pragma unroll
    for (int r = 0; r < 8; r++, idx += 256) {
      int c = idx >> 5, m = idx & 31;
      Bs[c * 36 + m] = V[(size_t)(c0 + c) * HW + m0 + m];
    }
    __syncthreads();
    #pragma unroll
    for (int m4 = 0; m4 < 8; m4++) {
      ulonglong2 a[4], b[4];
      #pragma unroll
      for (int i = 0; i < 4; i++)
        a[i] = *(const ulonglong2*)(As + (ng * 4 + i) * 36 + m4 * 4);
      #pragma unroll
      for (int j = 0; j < 4; j++)
        b[j] = *(const ulonglong2*)(Bs + (cg * 4 + j) * 36 + m4 * 4);
      #pragma unroll
      for (int i = 0; i < 4; i++)
        #pragma unroll
        for (int j = 0; j < 4; j++) {
          fma2(acc[i][j], a[i].x, b[j].x);
          fma2(acc[i][j], a[i].y, b[j].y);
        }
    }
    __syncthreads();
  }
  #pragma unroll
  for (int i = 0; i < 4; i++)
    #pragma unroll
    for (int j = 0; j < 4; j++)
      Cs[(ng * 4 + i) * 65 + cg * 4 + j] = red2(acc[i][j]);
  __syncthreads();
  int idx = t;
  #pragma unroll
  for (int r = 0; r < 16; r++, idx += 256) {
    int c = idx >> 6, n = idx & 63;
    size_t g = (size_t)(s * CD + c0 + c) * HW + n0 + n;
    tout[g] = tgt[g] + Cs[n * 65 + c];
  }
}

// ================= instance norm =================
__global__ __launch_bounds__(256) void instnorm_kernel(float* __restrict__ x) {
  __shared__ float redS[8];
  __shared__ float redQ[8];
  float* p = x + (size_t)blockIdx.x * HW;
  int t = threadIdx.x, lane = t & 31, warp = t >> 5;
  float v0 = p[t], v1 = p[t + 256], v2 = p[t + 512], v3 = p[t + 768];
  float sum = v0 + v1 + v2 + v3;
  float sq = v0 * v0 + v1 * v1 + v2 * v2 + v3 * v3;
  #pragma unroll
  for (int o = 16; o; o >>= 1) {
    sum += __shfl_xor_sync(0xffffffffu, sum, o);
    sq  += __shfl_xor_sync(0xffffffffu, sq, o);
  }
  if (lane == 0) { redS[warp] = sum; redQ[warp] = sq; }
  __syncthreads();
  sum = redS[0]; sq = redQ[0];
  #pragma unroll
  for (int i = 1; i < 8; i++) { sum += redS[i]; sq += redQ[i]; }
  float mean = sum * (1.0f / HW);
  float var = sq * (1.0f / HW) - mean * mean;
  float rstd = rsqrtf(var + 1e-5f);
  p[t]       = (v0 - mean) * rstd;
  p[t + 256] = (v1 - mean) * rstd;
  p[t + 512] = (v2 - mean) * rstd;
  p[t + 768] = (v3 - mean) * rstd;
}

// ================= cross attention: flash-style, block-parallel softmax =================
__global__ __launch_bounds__(256) void cross_attn_kernel(
    const float* __restrict__ wq, const float* __restrict__ wk,
    const float* __restrict__ pe, float* __restrict__ part) {
  extern __shared__ float sm[];
  float* Qs   = sm;                  // [64][132]
  float* Ks   = Qs + 64 * 132;       // [64][132]
  float* Ps   = Ks + 64 * 132;       // [64][65]
  float* Vs   = Ps + 64 * 65;        // [64][16]
  float* Os   = Vs + 64 * 16;        // [64][16]
  float* Om   = Os + 64 * 16;        // [64]
  float* Ol   = Om + 64;             // [64]
  float* Msc  = Ol + 64;             // [64] rescale factor per row
  float* Pred = Msc + 64;            // [64][16] partials
  int qt = blockIdx.x, s = blockIdx.y, ksp = blockIdx.z;
  int q0 = qt * 64;
  int t = threadIdx.x;
  // load Q tile (float4)
  {
    const float4* src = (const float4*)(wq + ((size_t)s * HW + q0) * KD);
    int idx = t;
    #pragma unroll
    for (int r = 0; r < 8; r++, idx += 256) {
      int q = idx >> 5, d4 = idx & 31;
      *(float4*)(Qs + q * 132 + d4 * 4) = src[idx];
    }
  }
  if (t < 64) { Om[t] = -1e30f; Ol[t] = 0.0f; Msc[t] = 0.0f; }
  {
    int idx = t;
    #pragma unroll
    for (int r = 0; r < 4; r++, idx += 256) Os[idx] = 0.0f;
  }
  int qg = t & 15, kg = t >> 4;
  const ulonglong2* qp[4];
  #pragma unroll
  for (int i = 0; i < 4; i++)
    qp[i] = (const ulonglong2*)(Qs + (qg * 4 + i) * 132);
  int pvq = t >> 2, pve = (t & 3) * 4;   // PV mapping

  for (int kt = 0; kt < NM / (KSPLIT * 64); kt++) {
    int kk0 = ksp * (NM / KSPLIT) + kt * 64;
    __syncthreads();   // prev PV done before overwriting Ks/Vs
    {
      const float4* src = (const float4*)(wk + ((size_t)s * NM + kk0) * KD);
      int idx = t;
      #pragma unroll
      for (int r = 0; r < 8; r++, idx += 256) {
        int k = idx >> 5, d4 = idx & 31;
        *(float4*)(Ks + k * 132 + d4 * 4) = src[idx];
      }
    }
    {
      int f = kk0 >> 10, nn0 = kk0 & 1023;
      const float* pb = pe + ((size_t)(f * S4 + s)) * CE * HW + nn0;
      int idx = t;
      #pragma unroll
      for (int r = 0; r < 4; r++, idx += 256) {
        int e = idx >> 6, k = idx & 63;
        Vs[k * 16 + e] = pb[(size_t)e * HW + k];
      }
    }
    __syncthreads();
    // ---- scores: 4x4 per thread, packed f32x2 ----
    ull acc2[4][4] = {};
    const ulonglong2* kp[4];
    #pragma unroll
    for (int j = 0; j < 4; j++)
      kp[j] = (const ulonglong2*)(Ks + (kg * 4 + j) * 132);
    #pragma unroll 4
    for (int d4 = 0; d4 < 32; d4++) {
      ulonglong2 a[4], b[4];
      #pragma unroll
      for (int i = 0; i < 4; i++) a[i] = qp[i][d4];
      #pragma unroll
      for (int j = 0; j < 4; j++) b[j] = kp[j][d4];
      #pragma unroll
      for (int i = 0; i < 4; i++)
        #pragma unroll
        for (int j = 0; j < 4; j++) {
          fma2(acc2[i][j], a[i].x, b[j].x);
          fma2(acc2[i][j], a[i].y, b[j].y);
        }
    }
    float acc[4][4];
    #pragma unroll
    for (int i = 0; i < 4; i++)
      #pragma unroll
      for (int j = 0; j < 4; j++)
        acc[i][j] = red2(acc2[i][j]) * TAU_INV;
    // ---- tile row-max partials ----
    #pragma unroll
    for (int i = 0; i < 4; i++) {
      float tm = fmaxf(fmaxf(acc[i][0], acc[i][1]), fmaxf(acc[i][2], acc[i][3]));
      Pred[(qg * 4 + i) * 16 + kg] = tm;
    }
    __syncthreads();
    if (t < 64) {
      float m = Pred[t * 16];
      #pragma unroll
      for (int i = 1; i < 16; i++) m = fmaxf(m, Pred[t * 16 + i]);
      float mo = Om[t];
      float M = fmaxf(mo, m);
      Msc[t] = __expf(mo - M);
      Om[t] = M;
    }
    __syncthreads();
    // ---- exp + row-sum partials ----
    #pragma unroll
    for (int i = 0; i < 4; i++) {
      int row = qg * 4 + i;
      float M = Om[row];
      float p0 = __expf(acc[i][0] - M), p1 = __expf(acc[i][1] - M);
      float p2 = __expf(acc[i][2] - M), p3 = __expf(acc[i][3] - M);
      Ps[row * 65 + kg * 4 + 0] = p0; Ps[row * 65 + kg * 4 + 1] = p1;
      Ps[row * 65 + kg * 4 + 2] = p2; Ps[row * 65 + kg * 4 + 3] = p3;
      Pred[row * 16 + kg] = p0 + p1 + p2 + p3;
    }
    __syncthreads();
    if (t < 64) {
      float sum = 0.0f;
      #pragma unroll
      for (int i = 0; i < 16; i++) sum += Pred[t * 16 + i];
      Ol[t] = Ol[t] * Msc[t] + sum;
    }
    // ---- PV: thread = (q, 4 e's), packed f32x2 ----
    {
      float scl = Msc[pvq];
      ull od = dup2(scl);
      ulonglong2 o = *(ulonglong2*)(Os + pvq * 16 + pve);
      // scale old O by scl
      ull zero0 = 0ULL, zero1 = 0ULL;
      fma2(zero0, o.x, od);
      fma2(zero1, o.y, od);
      o.x = zero0; o.y = zero1;
      const float* prow = Ps + pvq * 65;
      #pragma unroll 8
      for (int k = 0; k < 64; k++) {
        ull pp = dup2(prow[k]);
        ulonglong2 v = *(const ulonglong2*)(Vs + k * 16 + pve);
        fma2(o.x, pp, v.x);
        fma2(o.y, pp, v.y);
      }
      *(ulonglong2*)(Os + pvq * 16 + pve) = o;
    }
  }
  __syncthreads();
  if (t < 64) {
    float* pp = part + ((size_t)((ksp * S4 + s) * HW) + q0 + t) * 18;
    #pragma unroll
    for (int e = 0; e < 16; e++) pp[e] = Os[t * 16 + e];
    pp[16] = Om[t];
    pp[17] = Ol[t];
  }
}

// ================= merge split-K partials + sigmoid =================
__global__ __launch_bounds__(256) void merge_kernel(
    const float* __restrict__ part, float* __restrict__ out) {
  int t = blockIdx.x * 256 + threadIdx.x;  // 4096 threads = (s, n)
  int n = t & 1023, s = t >> 10;
  float M = -1e30f;
  #pragma unroll
  for (int z = 0; z < KSPLIT; z++)
    M = fmaxf(M, part[((size_t)((z * S4 + s) * HW) + n) * 18 + 16]);
  float L = 0.0f;
  float O[CE];
  #pragma unroll
  for (int e = 0; e < CE; e++) O[e] = 0.0f;
  #pragma unroll
  for (int z = 0; z < KSPLIT; z++) {
    const float* pp = part + ((size_t)((z * S4 + s) * HW) + n) * 18;
    float w = __expf(pp[16] - M);
    L += pp[17] * w;
    #pragma unroll
    for (int e = 0; e < CE; e++) O[e] += pp[e] * w;
  }
  float inv = 1.0f / L;
  #pragma unroll
  for (int e = 0; e < CE; e++) {
    float v = O[e] * inv;
    out[(size_t)(s * CE + e) * HW + n] = 1.0f / (1.0f + __expf(-v));
  }
}

// ================= host =================
extern "C" void kernel_launch(void* const* d_in, const int* in_sizes, int n_in,
                              void* d_out, int out_size) {
  const float* tgt = (const float*)d_in[0];
  const float* mem = (const float*)d_in[1];
  const float* pe  = (const float*)d_in[2];
  const float* wks = (const float*)d_in[3];
  const float* bks = (const float*)d_in[4];
  const float* wkc = (const float*)d_in[5];
  const float* bkc = (const float*)d_in[6];
  float* out = (float*)d_out;

  float *p_wq_self, *p_sc, *p_t, *p_wq_cross, *p_wk_cross, *p_part;
  cudaGetSymbolAddress((void**)&p_wq_self, g_wq_self);
  cudaGetSymbolAddress((void**)&p_sc, g_sc);
  cudaGetSymbolAddress((void**)&p_t, g_t);
  cudaGetSymbolAddress((void**)&p_wq_cross, g_wq_cross);
  cudaGetSymbolAddress((void**)&p_wk_cross, g_wk_cross);
  cudaGetSymbolAddress((void**)&p_part, g_part);

  // self-attention
  proj_kernel<<<dim3(32, 4), 256>>>(tgt, wks, bks, p_wq_self, HW);
  self_scores_kernel<<<dim3(16, 16, 4), 256>>>(p_wq_self, p_sc);
  softmax_kernel<<<4096, 256>>>(p_sc);
  pv_self_kernel<<<dim3(16, 8, 4), 256>>>(p_sc, tgt, p_t);
  instnorm_kernel<<<2048, 256>>>(p_t);

  // cross-attention projections
  proj_kernel<<<dim3(32, 4), 256>>>(p_t, wkc, bkc, p_wq_cross, HW);
  proj_kernel<<<dim3(512, 4), 256>>>(mem, wkc, bkc, p_wk_cross, NM);

  // flash cross-attention with split-K=8
  const int smem_bytes = (64 * 132 * 2 + 64 * 65 + 64 * 16 * 2 + 64 * 3 + 64 * 16) * 4;
  cudaFuncSetAttribute(cross_attn_kernel,
                       cudaFuncAttributeMaxDynamicSharedMemorySize, smem_bytes);
  cross_attn_kernel<<<dim3(16, 4, KSPLIT), 256, smem_bytes>>>(p_wq_cross, p_wk_cross, pe, p_part);
  merge_kernel<<<16, 256>>>(p_part, out);
}

// round 4
// speedup vs baseline: 2.2734x; 2.2734x over previous
#include <cuda_runtime.h>
#include <math.h>

#define S4 4
#define CD 512
#define KD 128
#define HW 1024
#define NM 16384
#define CE 16
#define TAU_INV 30.0f
#define KSPLIT 16

// ---------------- scratch (device globals; no allocation allowed) ----------------
__device__ float g_wq_self[S4 * HW * KD];
__device__ float g_sc[S4 * HW * HW];
__device__ float g_t[S4 * CD * HW];
__device__ float g_wq_cross[S4 * HW * KD];
__device__ float g_wk_cross[S4 * NM * KD];
__device__ float g_part[KSPLIT * S4 * HW * 18];

// ================= projection + L2 normalize =================
// in layout: [(f*S4+s)*CD + c]*HW + n ; out [s][token][d]
// 64 tokens x 128 d per block; thread tile: 8 tok (warp-uniform) x 4 d (strided +32)
__global__ __launch_bounds__(256) void proj_kernel(
    const float* __restrict__ in, const float* __restrict__ W,
    const float* __restrict__ bias, float* __restrict__ out, int NT) {
  __shared__ float As[64 * 36];    // [tok][cc]
  __shared__ float Ws[128 * 36];   // [d][cc]
  int s = blockIdx.y;
  int tg0 = blockIdx.x * 64;
  int f = tg0 >> 10;
  int n0 = tg0 & 1023;
  const float* inb = in + ((size_t)(f * S4 + s)) * CD * HW + n0;
  int t = threadIdx.x;
  int wid = t >> 5;    // token group: 8 tokens wid*8..+7 (warp-uniform)
  int dgr = t & 31;    // d rows: dgr + 32*j, j=0..3
  float acc[8][4] = {};
  for (int c0 = 0; c0 < CD; c0 += 32) {
    int idx = t;
    #pragma unroll
    for (int r = 0; r < 8; r++, idx += 256) {
      int cc = idx >> 6, tok = idx & 63;
      As[tok * 36 + cc] = inb[(size_t)(c0 + cc) * HW + tok];
    }
    idx = t;
    #pragma unroll
    for (int r = 0; r < 16; r++, idx += 256) {
      int d = idx >> 5, cc = idx & 31;
      Ws[d * 36 + cc] = W[d * CD + c0 + cc];
    }
    __syncthreads();
    #pragma unroll
    for (int cc4 = 0; cc4 < 8; cc4++) {
      float4 b[4];
      #pragma unroll
      for (int j = 0; j < 4; j++)
        b[j] = *(const float4*)(Ws + (dgr + 32 * j) * 36 + cc4 * 4);
      #pragma unroll
      for (int i = 0; i < 8; i++) {
        float4 a = *(const float4*)(As + (wid * 8 + i) * 36 + cc4 * 4);
        #pragma unroll
        for (int j = 0; j < 4; j++) {
          acc[i][j] = fmaf(a.x, b[j].x, acc[i][j]);
          acc[i][j] = fmaf(a.y, b[j].y, acc[i][j]);
          acc[i][j] = fmaf(a.z, b[j].z, acc[i][j]);
          acc[i][j] = fmaf(a.w, b[j].w, acc[i][j]);
        }
      }
    }
    __syncthreads();
  }
  float bv[4];
  #pragma unroll
  for (int j = 0; j < 4; j++) bv[j] = bias[dgr + 32 * j];
  float ssp[8];
  #pragma unroll
  for (int i = 0; i < 8; i++) {
    float s0 = 0.0f;
    #pragma unroll
    for (int j = 0; j < 4; j++) {
      acc[i][j] += bv[j];
      s0 = fmaf(acc[i][j], acc[i][j], s0);
    }
    ssp[i] = s0;
  }
  #pragma unroll
  for (int o = 16; o; o >>= 1)
    #pragma unroll
    for (int i = 0; i < 8; i++)
      ssp[i] += __shfl_xor_sync(0xffffffffu, ssp[i], o);
  #pragma unroll
  for (int i = 0; i < 8; i++) {
    float scl = 1.0f / fmaxf(sqrtf(ssp[i]), 1e-12f);
    float* ob = out + ((size_t)s * NT + tg0 + wid * 8 + i) * KD;
    #pragma unroll
    for (int j = 0; j < 4; j++)
      ob[dgr + 32 * j] = acc[i][j] * scl;
  }
}

// ================= self-attention raw scores (x30) =================
__global__ __launch_bounds__(256) void self_scores_kernel(
    const float* __restrict__ wq, float* __restrict__ sc) {
  __shared__ float QK[2][64][65];
  int s = blockIdx.z;
  int q0 = blockIdx.x * 64, k0 = blockIdx.y * 64;
  const float* base = wq + (size_t)s * HW * KD;
  int t = threadIdx.x;
  int qg = t & 15, kg = t >> 4;
  float acc[4][4] = {};
  for (int d0 = 0; d0 < KD; d0 += 64) {
    int idx = t;
    #pragma unroll
    for (int r = 0; r < 16; r++, idx += 256) {
      int row = idx >> 6, dd = idx & 63;
      QK[0][row][dd] = base[(size_t)(q0 + row) * KD + d0 + dd];
      QK[1][row][dd] = base[(size_t)(k0 + row) * KD + d0 + dd];
    }
    __syncthreads();
    #pragma unroll 8
    for (int k = 0; k < 64; k++) {
      float a[4], b[4];
      #pragma unroll
      for (int i = 0; i < 4; i++) a[i] = QK[0][qg * 4 + i][k];
      #pragma unroll
      for (int j = 0; j < 4; j++) b[j] = QK[1][kg * 4 + j][k];
      #pragma unroll
      for (int i = 0; i < 4; i++)
        #pragma unroll
        for (int j = 0; j < 4; j++)
          acc[i][j] = fmaf(a[i], b[j], acc[i][j]);
    }
    __syncthreads();
  }
  float* Cs = &QK[0][0][0];   // reuse as [64][65]
  #pragma unroll
  for (int i = 0; i < 4; i++)
    #pragma unroll
    for (int j = 0; j < 4; j++)
      Cs[(qg * 4 + i) * 65 + kg * 4 + j] = acc[i][j] * TAU_INV;
  __syncthreads();
  int idx = t;
  #pragma unroll
  for (int r = 0; r < 16; r++, idx += 256) {
    int row = idx >> 6, col = idx & 63;
    sc[((size_t)s * HW + q0 + row) * HW + k0 + col] = Cs[row * 65 + col];
  }
}

// ================= row softmax over 1024 =================
__global__ __launch_bounds__(256) void softmax_kernel(float* __restrict__ sc) {
  __shared__ float redm[8];
  __shared__ float reds[8];
  float* p = sc + (size_t)blockIdx.x * HW;
  int t = threadIdx.x, lane = t & 31, warp = t >> 5;
  float v0 = p[t], v1 = p[t + 256], v2 = p[t + 512], v3 = p[t + 768];
  float mx = fmaxf(fmaxf(v0, v1), fmaxf(v2, v3));
  #pragma unroll
  for (int o = 16; o; o >>= 1) mx = fmaxf(mx, __shfl_xor_sync(0xffffffffu, mx, o));
  if (lane == 0) redm[warp] = mx;
  __syncthreads();
  mx = redm[0];
  #pragma unroll
  for (int i = 1; i < 8; i++) mx = fmaxf(mx, redm[i]);
  v0 = __expf(v0 - mx); v1 = __expf(v1 - mx);
  v2 = __expf(v2 - mx); v3 = __expf(v3 - mx);
  float sum = v0 + v1 + v2 + v3;
  #pragma unroll
  for (int o = 16; o; o >>= 1) sum += __shfl_xor_sync(0xffffffffu, sum, o);
  if (lane == 0) reds[warp] = sum;
  __syncthreads();
  float tot = reds[0];
  #pragma unroll
  for (int i = 1; i < 8; i++) tot += reds[i];
  float inv = 1.0f / tot;
  p[t] = v0 * inv; p[t + 256] = v1 * inv;
  p[t + 512] = v2 * inv; p[t + 768] = v3 * inv;
}

// ================= self P.V + residual =================
// 128 n x 64 c per block; thread: 8 n (warp-uniform-ish) x 4 c (strided +16)
__global__ __launch_bounds__(256) void pv_self_kernel(
    const float* __restrict__ sc, const float* __restrict__ tgt,
    float* __restrict__ tout) {
  __shared__ float As[128 * 36];  // [n][m]
  __shared__ float Bs[64 * 36];   // [c][m]
  int s = blockIdx.z;
  int n0 = blockIdx.x * 128, c0 = blockIdx.y * 64;
  const float* P = sc + (size_t)s * HW * HW;
  const float* V = tgt + (size_t)s * CD * HW;
  int t = threadIdx.x;
  int cgr = t & 15;   // c rows: cgr + 16*j
  int ngr = t >> 4;   // n rows: ngr*8..+7
  float acc[8][4] = {};
  for (int m0 = 0; m0 < HW; m0 += 32) {
    int idx = t;
    #pragma unroll
    for (int r = 0; r < 16; r++, idx += 256) {
      int n = idx >> 5, m = idx & 31;
      As[n * 36 + m] = P[(size_t)(n0 + n) * HW + m0 + m];
    }
    idx = t;
    #pragma unroll
    for (int r = 0; r < 8; r++, idx += 256) {
      int c = idx >> 5, m = idx & 31;
      Bs[c * 36 + m] = V[(size_t)(c0 + c) * HW + m0 + m];
    }
    __syncthreads();
    #pragma unroll
    for (int m4 = 0; m4 < 8; m4++) {
      float4 b[4];
      #pragma unroll
      for (int j = 0; j < 4; j++)
        b[j] = *(const float4*)(Bs + (cgr + 16 * j) * 36 + m4 * 4);
      #pragma unroll
      for (int i = 0; i < 8; i++) {
        float4 a = *(const float4*)(As + (ngr * 8 + i) * 36 + m4 * 4);
        #pragma unroll
        for (int j = 0; j < 4; j++) {
          acc[i][j] = fmaf(a.x, b[j].x, acc[i][j]);
          acc[i][j] = fmaf(a.y, b[j].y, acc[i][j]);
          acc[i][j] = fmaf(a.z, b[j].z, acc[i][j]);
          acc[i][j] = fmaf(a.w, b[j].w, acc[i][j]);
        }
      }
    }
    __syncthreads();
  }
  #pragma unroll
  for (int j = 0; j < 4; j++) {
    int c = c0 + cgr + 16 * j;
    size_t g = (size_t)(s * CD + c) * HW + n0 + ngr * 8;
    #pragma unroll
    for (int i4 = 0; i4 < 8; i4 += 4) {
      float4 tg4 = *(const float4*)(tgt + g + i4);
      tg4.x += acc[i4 + 0][j]; tg4.y += acc[i4 + 1][j];
      tg4.z += acc[i4 + 2][j]; tg4.w += acc[i4 + 3][j];
      *(float4*)(tout + g + i4) = tg4;
    }
  }
}

// ================= instance norm =================
__global__ __launch_bounds__(256) void instnorm_kernel(float* __restrict__ x) {
  __shared__ float redS[8];
  __shared__ float redQ[8];
  float* p = x + (size_t)blockIdx.x * HW;
  int t = threadIdx.x, lane = t & 31, warp = t >> 5;
  float v0 = p[t], v1 = p[t + 256], v2 = p[t + 512], v3 = p[t + 768];
  float sum = v0 + v1 + v2 + v3;
  float sq = v0 * v0 + v1 * v1 + v2 * v2 + v3 * v3;
  #pragma unroll
  for (int o = 16; o; o >>= 1) {
    sum += __shfl_xor_sync(0xffffffffu, sum, o);
    sq  += __shfl_xor_sync(0xffffffffu, sq, o);
  }
  if (lane == 0) { redS[warp] = sum; redQ[warp] = sq; }
  __syncthreads();
  sum = redS[0]; sq = redQ[0];
  #pragma unroll
  for (int i = 1; i < 8; i++) { sum += redS[i]; sq += redQ[i]; }
  float mean = sum * (1.0f / HW);
  float var = sq * (1.0f / HW) - mean * mean;
  float rstd = rsqrtf(var + 1e-5f);
  p[t]       = (v0 - mean) * rstd;
  p[t + 256] = (v1 - mean) * rstd;
  p[t + 512] = (v2 - mean) * rstd;
  p[t + 768] = (v3 - mean) * rstd;
}

// ================= cross attention: flash-style, 64q x 128k tiles =================
__global__ __launch_bounds__(256, 1) void cross_attn_kernel(
    const float* __restrict__ wq, const float* __restrict__ wk,
    const float* __restrict__ pe, float* __restrict__ part) {
  extern __shared__ float sm[];
  float* Qs   = sm;                  // [64][132]
  float* Ks   = Qs + 64 * 132;       // [128][132]
  float* Ps   = Ks + 128 * 132;      // [64][132]
  float* Vs   = Ps + 64 * 132;       // [128][16]
  float* Os   = Vs + 128 * 16;       // [64][16]
  float* Om   = Os + 64 * 16;        // [64]
  float* Ol   = Om + 64;             // [64]
  float* Msc  = Ol + 64;             // [64]
  float* Pred = Msc + 64;            // [64][17]
  int qt = blockIdx.x, s = blockIdx.y, ksp = blockIdx.z;
  int q0 = qt * 64;
  int t = threadIdx.x;
  int qgr = t & 15;   // q rows: qgr + 16*i, i=0..3
  int kgr = t >> 4;   // k rows: kgr*8..+7 (warp-uniform pairs)
  // load Q tile scaled by TAU_INV
  {
    const float4* src = (const float4*)(wq + ((size_t)s * HW + q0) * KD);
    int idx = t;
    #pragma unroll
    for (int r = 0; r < 8; r++, idx += 256) {
      int q = idx >> 5, d4 = idx & 31;
      float4 v = src[idx];
      v.x *= TAU_INV; v.y *= TAU_INV; v.z *= TAU_INV; v.w *= TAU_INV;
      *(float4*)(Qs + q * 132 + d4 * 4) = v;
    }
  }
  if (t < 64) { Om[t] = -1e30f; Ol[t] = 0.0f; Msc[t] = 0.0f; }
  {
    int idx = t;
    #pragma unroll
    for (int r = 0; r < 4; r++, idx += 256) Os[idx] = 0.0f;
  }
  int pvq = t >> 2, pve = (t & 3) * 4;

  for (int kt = 0; kt < NM / (KSPLIT * 128); kt++) {
    int kk0 = ksp * (NM / KSPLIT) + kt * 128;
    __syncthreads();   // protect Ks/Vs/Ps from prev iter consumers
    {
      const float4* src = (const float4*)(wk + ((size_t)s * NM + kk0) * KD);
      int idx = t;
      #pragma unroll
      for (int r = 0; r < 16; r++, idx += 256) {
        int k = idx >> 5, d4 = idx & 31;
        *(float4*)(Ks + k * 132 + d4 * 4) = src[idx];
      }
    }
    {
      int f = kk0 >> 10, nn0 = kk0 & 1023;
      const float* pb = pe + ((size_t)(f * S4 + s)) * CE * HW + nn0;
      int idx = t;
      #pragma unroll
      for (int r = 0; r < 8; r++, idx += 256) {
        int e = idx >> 7, k = idx & 127;
        Vs[k * 16 + e] = pb[(size_t)e * HW + k];
      }
    }
    __syncthreads();
    // ---- scores: 4q x 8k per thread ----
    float acc[4][8] = {};
    #pragma unroll 8
    for (int d4 = 0; d4 < 32; d4++) {
      float4 b[8];
      #pragma unroll
      for (int jj = 0; jj < 8; jj++)
        b[jj] = *(const float4*)(Ks + (kgr * 8 + jj) * 132 + d4 * 4);
      #pragma unroll
      for (int i = 0; i < 4; i++) {
        float4 a = *(const float4*)(Qs + (qgr + 16 * i) * 132 + d4 * 4);
        #pragma unroll
        for (int jj = 0; jj < 8; jj++) {
          acc[i][jj] = fmaf(a.x, b[jj].x, acc[i][jj]);
          acc[i][jj] = fmaf(a.y, b[jj].y, acc[i][jj]);
          acc[i][jj] = fmaf(a.z, b[jj].z, acc[i][jj]);
          acc[i][jj] = fmaf(a.w, b[jj].w, acc[i][jj]);
        }
      }
    }
    // ---- per-thread row-max partials ----
    #pragma unroll
    for (int i = 0; i < 4; i++) {
      float tm = acc[i][0];
      #pragma unroll
      for (int jj = 1; jj < 8; jj++) tm = fmaxf(tm, acc[i][jj]);
      Pred[(qgr + 16 * i) * 17 + kgr] = tm;
    }
    __syncthreads();
    if (t < 64) {
      float m = Pred[t * 17];
      #pragma unroll
      for (int i = 1; i < 16; i++) m = fmaxf(m, Pred[t * 17 + i]);
      float mo = Om[t];
      float M = fmaxf(mo, m);
      Msc[t] = __expf(mo - M);
      Om[t] = M;
    }
    __syncthreads();
    // ---- exp, write P, row-sum partials ----
    #pragma unroll
    for (int i = 0; i < 4; i++) {
      int row = qgr + 16 * i;
      float M = Om[row];
      float psum = 0.0f;
      float4 p0, p1;
      p0.x = __expf(acc[i][0] - M); p0.y = __expf(acc[i][1] - M);
      p0.z = __expf(acc[i][2] - M); p0.w = __expf(acc[i][3] - M);
      p1.x = __expf(acc[i][4] - M); p1.y = __expf(acc[i][5] - M);
      p1.z = __expf(acc[i][6] - M); p1.w = __expf(acc[i][7] - M);
      psum = p0.x + p0.y + p0.z + p0.w + p1.x + p1.y + p1.z + p1.w;
      *(float4*)(Ps + row * 132 + kgr * 8) = p0;
      *(float4*)(Ps + row * 132 + kgr * 8 + 4) = p1;
      Pred[row * 17 + kgr] = psum;
    }
    __syncthreads();
    if (t < 64) {
      float sum = 0.0f;
      #pragma unroll
      for (int i = 0; i < 16; i++) sum += Pred[t * 17 + i];
      Ol[t] = Ol[t] * Msc[t] + sum;
    }
    // ---- PV: thread = (q, 4 e's) ----
    {
      float scl = Msc[pvq];
      float4 o = *(float4*)(Os + pvq * 16 + pve);
      o.x *= scl; o.y *= scl; o.z *= scl; o.w *= scl;
      const float* prow = Ps + pvq * 132;
      #pragma unroll 8
      for (int k = 0; k < 128; k++) {
        float p = prow[k];
        float4 v = *(const float4*)(Vs + k * 16 + pve);
        o.x = fmaf(p, v.x, o.x); o.y = fmaf(p, v.y, o.y);
        o.z = fmaf(p, v.z, o.z); o.w = fmaf(p, v.w, o.w);
      }
      *(float4*)(Os + pvq * 16 + pve) = o;
    }
  }
  __syncthreads();
  if (t < 64) {
    float* pp = part + ((size_t)((ksp * S4 + s) * HW) + q0 + t) * 18;
    #pragma unroll
    for (int e = 0; e < 16; e++) pp[e] = Os[t * 16 + e];
    pp[16] = Om[t];
    pp[17] = Ol[t];
  }
}

// ================= merge split-K partials + sigmoid =================
__global__ __launch_bounds__(256) void merge_kernel(
    const float* __restrict__ part, float* __restrict__ out) {
  int g = blockIdx.x * 256 + threadIdx.x;   // 16384 threads = (s,n) x 4 e-groups
  int eg = (g & 3) * 4;
  int sn = g >> 2;
  int n = sn & 1023, s = sn >> 10;
  float M = -1e30f;
  #pragma unroll
  for (int z = 0; z < KSPLIT; z++)
    M = fmaxf(M, part[((size_t)((z * S4 + s) * HW) + n) * 18 + 16]);
  float L = 0.0f;
  float O[4] = {};
  #pragma unroll
  for (int z = 0; z < KSPLIT; z++) {
    const float* pp = part + ((size_t)((z * S4 + s) * HW) + n) * 18;
    float w = __expf(pp[16] - M);
    L += pp[17] * w;
    #pragma unroll
    for (int e = 0; e < 4; e++) O[e] += pp[eg + e] * w;
  }
  float inv = 1.0f / L;
  #pragma unroll
  for (int e = 0; e < 4; e++) {
    float v = O[e] * inv;
    out[(size_t)(s * CE + eg + e) * HW + n] = 1.0f / (1.0f + __expf(-v));
  }
}

// ================= host =================
extern "C" void kernel_launch(void* const* d_in, const int* in_sizes, int n_in,
                              void* d_out, int out_size) {
  const float* tgt = (const float*)d_in[0];
  const float* mem = (const float*)d_in[1];
  const float* pe  = (const float*)d_in[2];
  const float* wks = (const float*)d_in[3];
  const float* bks = (const float*)d_in[4];
  const float* wkc = (const float*)d_in[5];
  const float* bkc = (const float*)d_in[6];
  float* out = (float*)d_out;

  float *p_wq_self, *p_sc, *p_t, *p_wq_cross, *p_wk_cross, *p_part;
  cudaGetSymbolAddress((void**)&p_wq_self, g_wq_self);
  cudaGetSymbolAddress((void**)&p_sc, g_sc);
  cudaGetSymbolAddress((void**)&p_t, g_t);
  cudaGetSymbolAddress((void**)&p_wq_cross, g_wq_cross);
  cudaGetSymbolAddress((void**)&p_wk_cross, g_wk_cross);
  cudaGetSymbolAddress((void**)&p_part, g_part);

  // self-attention
  proj_kernel<<<dim3(16, 4), 256>>>(tgt, wks, bks, p_wq_self, HW);
  self_scores_kernel<<<dim3(16, 16, 4), 256>>>(p_wq_self, p_sc);
  softmax_kernel<<<4096, 256>>>(p_sc);
  pv_self_kernel<<<dim3(8, 8, 4), 256>>>(p_sc, tgt, p_t);
  instnorm_kernel<<<2048, 256>>>(p_t);

  // cross-attention projections
  proj_kernel<<<dim3(16, 4), 256>>>(p_t, wkc, bkc, p_wq_cross, HW);
  proj_kernel<<<dim3(256, 4), 256>>>(mem, wkc, bkc, p_wk_cross, NM);

  // flash cross-attention with split-K=16
  const int smem_bytes = (64 * 132 + 128 * 132 + 64 * 132 + 128 * 16 +
                          64 * 16 + 64 * 3 + 64 * 17) * 4;   // 152576 B
  cudaFuncSetAttribute(cross_attn_kernel,
                       cudaFuncAttributeMaxDynamicSharedMemorySize, smem_bytes);
  cross_attn_kernel<<<dim3(16, 4, KSPLIT), 256, smem_bytes>>>(p_wq_cross, p_wk_cross, pe, p_part);
  merge_kernel<<<64, 256>>>(p_part, out);
}